// round 5
// baseline (speedup 1.0000x reference)
#include <cuda_runtime.h>
#include <math.h>
#include <stdint.h>

// Problem constants (fixed by the dataset)
#define D      128
#define BT     32
#define LSEQ   256
#define NTOK   (BT*LSEQ)     // 8192
#define NHEAD  8
#define DK     16
#define DI     512
#define NMAX   100000
#define NLAYER 2

// ---------------- scratch (device globals) ----------------
__device__ float g_side[(size_t)NMAX * D];
__device__ float g_x[(size_t)NTOK * D];
__device__ float g_q[(size_t)NTOK * D];
__device__ float g_k[(size_t)NTOK * D];
__device__ float g_v[(size_t)NTOK * D];
__device__ float g_o[(size_t)NTOK * D];
__device__ float g_t[(size_t)NTOK * D];
__device__ float g_h[(size_t)NTOK * DI];

// ---------------- utility kernels ----------------
__global__ void zero_kernel(float* __restrict__ p, int n4) {
    int i = blockIdx.x * blockDim.x + threadIdx.x;
    if (i < n4) ((float4*)p)[i] = make_float4(0.f, 0.f, 0.f, 0.f);
}

// ---------------- sorted-COO SpMM with run-length accumulation ----------------
#define EPB 256
__global__ __launch_bounds__(D) void spmm_kernel(
    const float* __restrict__ vals, const int* __restrict__ rows,
    const int* __restrict__ cols, const float* __restrict__ ego,
    float* __restrict__ side, int nnz)
{
    __shared__ int   s_row[EPB];
    __shared__ int   s_col[EPB];
    __shared__ float s_val[EPB];
    int e0 = blockIdx.x * EPB;
    int cnt = min(EPB, nnz - e0);
    if (cnt <= 0) return;
    for (int i = threadIdx.x; i < cnt; i += blockDim.x) {
        s_row[i] = rows[e0 + i];
        s_col[i] = cols[e0 + i];
        s_val[i] = vals[e0 + i];
    }
    __syncthreads();
    int t = threadIdx.x;
    float acc = 0.f;
    int cur = s_row[0];
    for (int i = 0; i < cnt; i++) {
        int r = s_row[i];
        if (r != cur) {
            atomicAdd(&side[(size_t)cur * D + t], acc);
            acc = 0.f;
            cur = r;
        }
        acc = fmaf(s_val[i], __ldg(&ego[(size_t)s_col[i] * D + t]), acc);
    }
    atomicAdd(&side[(size_t)cur * D + t], acc);
}

// ---------------- tf32x3 tensor-core GEMM (hi/lo split at load time) ------------
// C[M,N] = epi(Aop[M,K] @ W[K,N]); Aop: A (ASRC=0), A+A2 (1), A*A2 (2)
// Block tile 64x128x8, 8 warps (2m x 4n), warp tile 32x32 via m16n8k8.
#define GBM 64
#define GBN 128
#define GBK 8
#define ASTR 72      // stride mod 32 == 8 -> fragment reads conflict-free
#define BSTR 136

__device__ __forceinline__ uint32_t f2tf(float f) {
    uint32_t u;
    asm("cvt.rna.tf32.f32 %0, %1;" : "=r"(u) : "f"(f));
    return u;
}

__device__ __forceinline__ void mma8(float* c, const uint32_t* a, const uint32_t* b) {
    asm volatile(
        "mma.sync.aligned.m16n8k8.row.col.f32.tf32.tf32.f32 "
        "{%0,%1,%2,%3}, {%4,%5,%6,%7}, {%8,%9}, {%0,%1,%2,%3};"
        : "+f"(c[0]), "+f"(c[1]), "+f"(c[2]), "+f"(c[3])
        : "r"(a[0]), "r"(a[1]), "r"(a[2]), "r"(a[3]), "r"(b[0]), "r"(b[1]));
}

template<int ASRC, int ACT, bool ACCUM, bool HASRES>
__global__ __launch_bounds__(256, 3) void gemm_tc(
    const float* __restrict__ A, const float* __restrict__ A2,
    const float* __restrict__ W, const float* __restrict__ bias,
    const float* __restrict__ res, float* __restrict__ C,
    int M, int N, int K)
{
    __shared__ uint32_t As_hi[2][GBK][ASTR];
    __shared__ uint32_t As_lo[2][GBK][ASTR];
    __shared__ uint32_t Bs_hi[2][GBK][BSTR];
    __shared__ uint32_t Bs_lo[2][GBK][BSTR];

    const int tid  = threadIdx.x;
    const int wid  = tid >> 5;
    const int lane = tid & 31;
    const int wm   = (wid >> 2) * 32;
    const int wn   = (wid & 3) * 32;
    const int row0 = blockIdx.y * GBM;
    const int col0 = blockIdx.x * GBN;

    // A loader: thread -> (m row, k pair)
    const int al_m = tid >> 2;          // 0..63
    const int al_k = (tid & 3) * 2;     // 0,2,4,6
    const int grow = row0 + al_m;
    const bool aval = grow < M;
    const float* Ap  = A + (size_t)grow * K + al_k;
    const float* A2p = (ASRC ? A2 : A) + (size_t)grow * K + al_k;

    // B loader: thread -> (k row, n quad)
    const int bl_k = tid >> 5;          // 0..7
    const int bl_n = (tid & 31) * 4;    // 0..124
    const float* Wp = W + (size_t)bl_k * N + col0 + bl_n;

    float acc[2][4][4] = {};

    auto load_stage = [&](int k0, int buf) {
        float2 a = make_float2(0.f, 0.f);
        if (aval) {
            a = *(const float2*)(Ap + k0);
            if (ASRC) {
                float2 s = *(const float2*)(A2p + k0);
                if (ASRC == 1) { a.x += s.x; a.y += s.y; }
                else           { a.x *= s.x; a.y *= s.y; }
            }
        }
        uint32_t h0 = f2tf(a.x), h1 = f2tf(a.y);
        As_hi[buf][al_k + 0][al_m] = h0;
        As_hi[buf][al_k + 1][al_m] = h1;
        As_lo[buf][al_k + 0][al_m] = f2tf(a.x - __uint_as_float(h0));
        As_lo[buf][al_k + 1][al_m] = f2tf(a.y - __uint_as_float(h1));

        float4 b = *(const float4*)(Wp + (size_t)k0 * N);
        uint32_t bh0 = f2tf(b.x), bh1 = f2tf(b.y), bh2 = f2tf(b.z), bh3 = f2tf(b.w);
        *(uint4*)&Bs_hi[buf][bl_k][bl_n] = make_uint4(bh0, bh1, bh2, bh3);
        *(uint4*)&Bs_lo[buf][bl_k][bl_n] = make_uint4(
            f2tf(b.x - __uint_as_float(bh0)), f2tf(b.y - __uint_as_float(bh1)),
            f2tf(b.z - __uint_as_float(bh2)), f2tf(b.w - __uint_as_float(bh3)));
    };

    load_stage(0, 0);
    __syncthreads();

    const int nstages = K / GBK;
    const int fr = lane >> 2;
    const int fc = lane & 3;
    for (int s = 0; s < nstages; s++) {
        int buf = s & 1;
        if (s + 1 < nstages) load_stage((s + 1) * GBK, buf ^ 1);

        uint32_t ahi[2][4], alo[2][4], bhi[4][2], blo[4][2];
        #pragma unroll
        for (int mi = 0; mi < 2; mi++) {
            int r = wm + mi * 16 + fr;
            ahi[mi][0] = As_hi[buf][fc][r];
            ahi[mi][1] = As_hi[buf][fc][r + 8];
            ahi[mi][2] = As_hi[buf][fc + 4][r];
            ahi[mi][3] = As_hi[buf][fc + 4][r + 8];
            alo[mi][0] = As_lo[buf][fc][r];
            alo[mi][1] = As_lo[buf][fc][r + 8];
            alo[mi][2] = As_lo[buf][fc + 4][r];
            alo[mi][3] = As_lo[buf][fc + 4][r + 8];
        }
        #pragma unroll
        for (int ni = 0; ni < 4; ni++) {
            int n = wn + ni * 8 + fr;
            bhi[ni][0] = Bs_hi[buf][fc][n];
            bhi[ni][1] = Bs_hi[buf][fc + 4][n];
            blo[ni][0] = Bs_lo[buf][fc][n];
            blo[ni][1] = Bs_lo[buf][fc + 4][n];
        }
        #pragma unroll
        for (int mi = 0; mi < 2; mi++)
            #pragma unroll
            for (int ni = 0; ni < 4; ni++)
                mma8(acc[mi][ni], ahi[mi], bhi[ni]);
        #pragma unroll
        for (int mi = 0; mi < 2; mi++)
            #pragma unroll
            for (int ni = 0; ni < 4; ni++)
                mma8(acc[mi][ni], alo[mi], bhi[ni]);
        #pragma unroll
        for (int mi = 0; mi < 2; mi++)
            #pragma unroll
            for (int ni = 0; ni < 4; ni++)
                mma8(acc[mi][ni], ahi[mi], blo[ni]);
        __syncthreads();
    }

    // ---------------- epilogue ----------------
    #pragma unroll
    for (int mi = 0; mi < 2; mi++) {
        #pragma unroll
        for (int ni = 0; ni < 4; ni++) {
            int c = col0 + wn + ni * 8 + 2 * (lane & 3);
            float bi0 = bias[c], bi1 = bias[c + 1];
            #pragma unroll
            for (int half = 0; half < 2; half++) {
                int r = row0 + wm + mi * 16 + (lane >> 2) + half * 8;
                if (r >= M) continue;
                float v0 = acc[mi][ni][half * 2 + 0] + bi0;
                float v1 = acc[mi][ni][half * 2 + 1] + bi1;
                if (HASRES) {
                    float2 rr = *(const float2*)&res[(size_t)r * N + c];
                    v0 += rr.x; v1 += rr.y;
                }
                if (ACT == 1) { v0 = fmaxf(v0, 0.f); v1 = fmaxf(v1, 0.f); }
                else if (ACT == 2) {
                    v0 = (v0 > 0.f) ? v0 : 0.01f * v0;
                    v1 = (v1 > 0.f) ? v1 : 0.01f * v1;
                }
                if (ACCUM) {
                    float2 cc = *(const float2*)&C[(size_t)r * N + c];
                    v0 += cc.x; v1 += cc.y;
                }
                *(float2*)&C[(size_t)r * N + c] = make_float2(v0, v1);
            }
        }
    }
}

// ---------------- fused attention (per (batch, head) block, online softmax) -------
__global__ __launch_bounds__(LSEQ) void attn_kernel(
    const float* __restrict__ q, const float* __restrict__ k,
    const float* __restrict__ v, float* __restrict__ o)
{
    __shared__ float4 Ks[LSEQ][4];
    __shared__ float4 Vs[LSEQ][4];
    int b = blockIdx.x / NHEAD;
    int h = blockIdx.x % NHEAD;
    int t = threadIdx.x;

    size_t base = ((size_t)b * LSEQ + t) * D + h * DK;
    {
        const float4* kp = (const float4*)(k + base);
        const float4* vp = (const float4*)(v + base);
        #pragma unroll
        for (int i = 0; i < 4; i++) { Ks[t][i] = kp[i]; Vs[t][i] = vp[i]; }
    }
    __syncthreads();

    float4 qr[4];
    {
        const float4* qp = (const float4*)(q + base);
        #pragma unroll
        for (int i = 0; i < 4; i++) qr[i] = qp[i];
    }

    float mx = -1e30f, sm = 0.f;
    float4 oacc[4] = {};
    for (int m = 0; m < LSEQ; m++) {
        float s = 0.f;
        #pragma unroll
        for (int i = 0; i < 4; i++) {
            float4 kv = Ks[m][i];
            s = fmaf(qr[i].x, kv.x, s); s = fmaf(qr[i].y, kv.y, s);
            s = fmaf(qr[i].z, kv.z, s); s = fmaf(qr[i].w, kv.w, s);
        }
        s *= 0.25f;
        float nm = fmaxf(mx, s);
        float corr = __expf(mx - nm);
        float p    = __expf(s  - nm);
        sm = sm * corr + p;
        #pragma unroll
        for (int i = 0; i < 4; i++) {
            float4 vv4 = Vs[m][i];
            oacc[i].x = fmaf(oacc[i].x, corr, p * vv4.x);
            oacc[i].y = fmaf(oacc[i].y, corr, p * vv4.y);
            oacc[i].z = fmaf(oacc[i].z, corr, p * vv4.z);
            oacc[i].w = fmaf(oacc[i].w, corr, p * vv4.w);
        }
        mx = nm;
    }
    float inv = 1.f / sm;
    float4* op = (float4*)(o + base);
    #pragma unroll
    for (int i = 0; i < 4; i++)
        op[i] = make_float4(oacc[i].x*inv, oacc[i].y*inv, oacc[i].z*inv, oacc[i].w*inv);
}

// ---------------- LayerNorm (one warp per row of 128) ----------------
__global__ __launch_bounds__(128) void ln_kernel(
    const float* __restrict__ in, const float* __restrict__ g,
    const float* __restrict__ b, float* __restrict__ out)
{
    int row = blockIdx.x * 4 + (threadIdx.x >> 5);
    int lane = threadIdx.x & 31;
    const float4* p = (const float4*)(in + (size_t)row * D);
    float4 x = p[lane];
    float s  = x.x + x.y + x.z + x.w;
    float sq = x.x*x.x + x.y*x.y + x.z*x.z + x.w*x.w;
    #pragma unroll
    for (int off = 16; off; off >>= 1) {
        s  += __shfl_xor_sync(0xFFFFFFFFu, s,  off);
        sq += __shfl_xor_sync(0xFFFFFFFFu, sq, off);
    }
    float mean = s * (1.f / D);
    float var  = sq * (1.f / D) - mean * mean;
    float rs = rsqrtf(var + 1e-5f);
    float4 gg = ((const float4*)g)[lane];
    float4 bb = ((const float4*)b)[lane];
    float4 r;
    r.x = (x.x - mean) * rs * gg.x + bb.x;
    r.y = (x.y - mean) * rs * gg.y + bb.y;
    r.z = (x.z - mean) * rs * gg.z + bb.z;
    r.w = (x.w - mean) * rs * gg.w + bb.w;
    ((float4*)(out + (size_t)row * D))[lane] = r;
}

// ---------------- host launch ----------------
extern "C" void kernel_launch(void* const* d_in, const int* in_sizes, int n_in,
                              void* d_out, int out_size)
{
    const float* ego    = (const float*)d_in[0];
    const float* vals   = (const float*)d_in[1];
    const float* W1     = (const float*)d_in[2];
    const float* b1     = (const float*)d_in[3];
    const float* W2     = (const float*)d_in[4];
    const float* b2     = (const float*)d_in[5];
    const float* enc_in = (const float*)d_in[6];
    const float* wq     = (const float*)d_in[7];
    const float* bq     = (const float*)d_in[8];
    const float* wk     = (const float*)d_in[9];
    const float* bk     = (const float*)d_in[10];
    const float* wv     = (const float*)d_in[11];
    const float* bv     = (const float*)d_in[12];
    const float* wo     = (const float*)d_in[13];
    const float* bo     = (const float*)d_in[14];
    const float* ln1_g  = (const float*)d_in[15];
    const float* ln1_b  = (const float*)d_in[16];
    const float* cw1    = (const float*)d_in[17];
    const float* cb1    = (const float*)d_in[18];
    const float* cw2    = (const float*)d_in[19];
    const float* cb2    = (const float*)d_in[20];
    const float* ln2_g  = (const float*)d_in[21];
    const float* ln2_b  = (const float*)d_in[22];
    const int*   rows   = (const int*)d_in[23];
    const int*   cols   = (const int*)d_in[24];

    int N   = in_sizes[0] / D;
    int nnz = in_sizes[1];

    float* agg_out = (float*)d_out;
    float* x_out   = (float*)d_out + (size_t)N * D;

    float *side, *x, *q, *kk, *vv, *o, *t, *hh;
    cudaGetSymbolAddress((void**)&side, g_side);
    cudaGetSymbolAddress((void**)&x,    g_x);
    cudaGetSymbolAddress((void**)&q,    g_q);
    cudaGetSymbolAddress((void**)&kk,   g_k);
    cudaGetSymbolAddress((void**)&vv,   g_v);
    cudaGetSymbolAddress((void**)&o,    g_o);
    cudaGetSymbolAddress((void**)&t,    g_t);
    cudaGetSymbolAddress((void**)&hh,   g_h);

    // ---- stage 1: SpMM + bi-interaction ----
    int n4 = (N * D) / 4;
    zero_kernel<<<(n4 + 255) / 256, 256>>>(side, n4);
    spmm_kernel<<<(nnz + EPB - 1) / EPB, D>>>(vals, rows, cols, ego, side, nnz);

    dim3 gagg(1, (N + GBM - 1) / GBM);
    gemm_tc<1, 2, false, false><<<gagg, 256>>>(ego, side, W1, b1, nullptr, agg_out, N, D, D);
    gemm_tc<2, 2, true,  false><<<gagg, 256>>>(ego, side, W2, b2, nullptr, agg_out, N, D, D);

    // ---- stage 2: transformer encoder ----
    dim3 g1(1, NTOK / GBM);        // N=128 GEMMs: 128 blocks
    dim3 g2(DI / GBN, NTOK / GBM); // N=512 GEMM: 512 blocks
    for (int i = 0; i < NLAYER; i++) {
        const float* xin = (i == 0) ? enc_in : x;
        const float* wq_i  = wq  + (size_t)i * D * D;
        const float* wk_i  = wk  + (size_t)i * D * D;
        const float* wv_i  = wv  + (size_t)i * D * D;
        const float* wo_i  = wo  + (size_t)i * D * D;
        const float* cw1_i = cw1 + (size_t)i * D * DI;
        const float* cw2_i = cw2 + (size_t)i * DI * D;

        gemm_tc<0, 0, false, false><<<g1, 256>>>(xin, nullptr, wq_i, bq + i * D, nullptr, q,  NTOK, D, D);
        gemm_tc<0, 0, false, false><<<g1, 256>>>(xin, nullptr, wk_i, bk + i * D, nullptr, kk, NTOK, D, D);
        gemm_tc<0, 0, false, false><<<g1, 256>>>(xin, nullptr, wv_i, bv + i * D, nullptr, vv, NTOK, D, D);

        attn_kernel<<<BT * NHEAD, LSEQ>>>(q, kk, vv, o);

        // t = o@wo + bo + xin ; x = LN1(t)
        gemm_tc<0, 0, false, true><<<g1, 256>>>(o, nullptr, wo_i, bo + i * D, xin, t, NTOK, D, D);
        ln_kernel<<<NTOK / 4, 128>>>(t, ln1_g + i * D, ln1_b + i * D, x);

        // h = relu(x@cw1 + cb1)
        gemm_tc<0, 1, false, false><<<g2, 256>>>(x, nullptr, cw1_i, cb1 + i * DI, nullptr, hh, NTOK, DI, D);

        // t = h@cw2 + cb2 + x ; out = LN2(t)
        gemm_tc<0, 0, false, true><<<g1, 256>>>(hh, nullptr, cw2_i, cb2 + i * D, x, t, NTOK, D, DI);
        float* outp = (i == NLAYER - 1) ? x_out : x;
        ln_kernel<<<NTOK / 4, 128>>>(t, ln2_g + i * D, ln2_b + i * D, outp);
    }
}